// round 9
// baseline (speedup 1.0000x reference)
#include <cuda_runtime.h>
#include <cuda_bf16.h>

// Cost volume: out[n,c,d,h,w] = left[n,c,h,w] * right[n,c,h,w-d]  (0 if w<d)
// N=2 C=32 H=136 W=240 D=48, fp32.
//
// R8 state: pinned at 6.76 TB/s writes; wavefront/quantum levers all neutral.
// R9: DRAM page locality. CTA = (nc, 4-row h-block); all threads walk d
// together, so the CTA co-writes 3840B contiguous per d-plane (30 lines)
// before hopping planes: 4x larger bursts, ~12x fewer concurrent streams.
// Inner math unchanged: d = 4q+s -> 2 aligned LDS.128 serve 4 disparities;
// STG.128 streaming (__stcs).

#define NW   240
#define NH   136
#define NC   32
#define NN   2
#define ND   48
#define W4   60              // float4 columns per row
#define PADF 64              // zero floats in front of P
#define ROWSZ (PADF + NW)    // 304
#define RPB  4               // rows per CTA (NH % 4 == 0)
#define THREADS 256

__global__ __launch_bounds__(THREADS, 8)
void cost_volume_kernel(const float* __restrict__ left,
                        const float* __restrict__ right,
                        float* __restrict__ out) {
    // RPB padded right rows: buf[r][i] = P_r[i - PADF]
    __shared__ __align__(16) float buf[RPB][ROWSZ];

    const int blk  = blockIdx.x;           // blk = nc * (NH/RPB) + hb
    const int hb   = blk % (NH / RPB);
    const int nc   = blk / (NH / RPB);
    const int h0   = hb * RPB;
    const int tid  = threadIdx.x;

    // Cooperative staging of RPB padded rows (coalesced, conflict-free).
    const float* rbase = right + ((size_t)nc * NH + h0) * NW;
    for (int i = tid; i < RPB * ROWSZ; i += THREADS) {
        const int r = i / ROWSZ;
        const int j = i - r * ROWSZ;
        buf[r][j] = (j < PADF) ? 0.0f : rbase[(size_t)r * NW + j - PADF];
    }
    __syncthreads();

    // Thread mapping: r = tid/64 (row in block), c = tid%64 (float4 column).
    const int r = tid >> 6;                // 0..3
    const int c = tid & 63;                // float4 column, 60 active
    if (c >= W4) return;                   // no collectives below

    const int h = h0 + r;
    const float4 l4 =
        reinterpret_cast<const float4*>(left + ((size_t)nc * NH + h) * NW)[c];

    float* obase = out + ((size_t)nc * ND * NH + h) * NW + 4 * c;
    const float* P = buf[r] + PADF;        // P[x], x down to -64 valid

    #pragma unroll
    for (int q = 0; q < ND / 4; q++) {     // d-group: d = 4q+s, s = 0..3
        // Two aligned 16B smem loads cover all 4 disparities of this group.
        const float4 Y = *reinterpret_cast<const float4*>(P + 4 * (c - q));
        const float4 X = *reinterpret_cast<const float4*>(P + 4 * (c - q - 1));
        const float yv[4] = {Y.x, Y.y, Y.z, Y.w};
        const float xv[4] = {X.x, X.y, X.z, X.w};

        #pragma unroll
        for (int s = 0; s < 4; s++) {
            const int d = 4 * q + s;
            float4 v;
            // out[4c+i] uses P[4c+i-d] = (i>=s) ? Y[i-s] : X[i+4-s]  (static)
            v.x = l4.x * ((0 >= s) ? yv[0] : xv[4 - s]);
            v.y = l4.y * ((1 >= s) ? yv[(1 - s) & 3] : xv[(5 - s) & 3]);
            v.z = l4.z * ((2 >= s) ? yv[(2 - s) & 3] : xv[(6 - s) & 3]);
            v.w = l4.w * ((3 >= s) ? yv[(3 - s) & 3] : xv[(7 - s) & 3]);
            __stcs(reinterpret_cast<float4*>(obase + (size_t)d * (NH * NW)), v);
        }
    }
}

extern "C" void kernel_launch(void* const* d_in, const int* in_sizes, int n_in,
                              void* d_out, int out_size) {
    const float* left  = (const float*)d_in[0];
    const float* right = (const float*)d_in[1];
    float* out = (float*)d_out;

    const int grid = NN * NC * (NH / RPB);   // 2176 CTAs
    cost_volume_kernel<<<grid, THREADS>>>(left, right, out);
}